// round 15
// baseline (speedup 1.0000x reference)
#include <cuda_runtime.h>

#define B_    16
#define A_    262144
#define G_    128

// ---- prep launch: 4096 blocks x 256 thr, thread = 4 anchors of one batch
#define PTHR  256
#define PBLK  (B_ * A_ / (4 * PTHR))   /* 4096 */
#define CHUNKS_PER_B (A_ / (4 * PTHR)) /* 256 */

// ---- main launch: 1024 blocks x 128 thr, thread = 2 anchors
#define NTHR  128
#define ANCH  2
#define NBLK  (A_ / (ANCH * NTHR))     /* 1024 */
#define NWARP (NTHR / 32)              /* 4 */

// Pre-transformed gt table: {gcx, gcy, log(gw), log(gh)} per (b, g).
__device__ float4      g_gt[B_ * G_];
// int8 shadow of matched_idxs (values fit in [-2, 127]): 4.2 MB vs 16.8 MB.
__device__ signed char g_m8[B_ * A_];
// Per-batch fg counts (int atomics -> deterministic) and weights 1/max(1,n).
__device__ int         g_cnt[B_];
__device__ float       g_w[B_];
// Per-block weighted partials.
__device__ float       g_bpart[NBLK];
__device__ unsigned    g_done1 = 0;
__device__ unsigned    g_done2 = 0;

// ---------------------------------------------------------------------------
// K1 (lean): block = (batch, chunk). One int4 load + one char4 store per
// thread, one atomicAdd per block. Also pre-transforms gt (first 2048 gids).
// ---------------------------------------------------------------------------
__global__ void __launch_bounds__(PTHR)
prep_kernel(const float4* __restrict__ gt, const int* __restrict__ midx)
{
    __shared__ int s_c[PTHR / 32];
    __shared__ unsigned s_t;

    const int tid  = threadIdx.x;
    const int lane = tid & 31;
    const int warp = tid >> 5;

    const int gid = blockIdx.x * PTHR + tid;
    if (gid < B_ * G_) {
        float4 g = gt[gid];
        float gw = g.z - g.x;
        float gh = g.w - g.y;
        g_gt[gid] = make_float4(g.x + 0.5f * gw, g.y + 0.5f * gh,
                                __logf(gw), __logf(gh));
    }

    const int b     = blockIdx.x >> 8;          // / CHUNKS_PER_B
    const int chunk = blockIdx.x & (CHUNKS_PER_B - 1);
    const int idx   = b * A_ + chunk * (4 * PTHR) + tid * 4;

    int4 mv = __ldcs(reinterpret_cast<const int4*>(&midx[idx]));  // 16B load
    char4 pk;
    pk.x = (char)mv.x; pk.y = (char)mv.y; pk.z = (char)mv.z; pk.w = (char)mv.w;
    *reinterpret_cast<char4*>(&g_m8[idx]) = pk;                   // 4B store

    int c = (mv.x >= 0) + (mv.y >= 0) + (mv.z >= 0) + (mv.w >= 0);
#pragma unroll
    for (int o = 16; o > 0; o >>= 1)
        c += __shfl_down_sync(0xffffffffu, c, o);
    if (lane == 0) s_c[warp] = c;
    __syncthreads();

    if (tid == 0) {
        int tot = 0;
#pragma unroll
        for (int w = 0; w < PTHR / 32; w++) tot += s_c[w];
        atomicAdd(&g_cnt[b], tot);          // 4096 atomics total, 256/addr
        __threadfence();
        s_t = atomicAdd(&g_done1, 1u);
    }
    __syncthreads();

    if (s_t == (unsigned)(PBLK - 1)) {
        if (tid < B_) {
            int cc = g_cnt[tid];
            g_w[tid]   = 1.0f / (float)(cc > 1 ? cc : 1);
            g_cnt[tid] = 0;                 // reset for next graph replay
        }
        if (tid == 0) g_done1 = 0;
    }
}

// ---------------------------------------------------------------------------
// K2: R12's proven weighted stream-accumulate, now with TWO independent
// anchor streams per thread (doubles in-flight LDG.128) on a 1024x128 grid.
// ---------------------------------------------------------------------------
__global__ void __launch_bounds__(NTHR)
retina_loss_main(const float4* __restrict__ bbox,     // [B, A, 4]
                 const float4* __restrict__ anchors,  // [A, 4]
                 float*        __restrict__ out)
{
    __shared__ float s_w[B_];
    __shared__ float s_sum[NWARP];
    __shared__ unsigned s_t;

    const int tid  = threadIdx.x;
    const int lane = tid & 31;
    const int warp = tid >> 5;
    const int base = blockIdx.x * (ANCH * NTHR);
    const int a0   = base + tid;
    const int a1   = base + NTHR + tid;

    if (tid < B_) s_w[tid] = g_w[tid];

    // Two anchors, each loaded ONCE, reused for all 16 batches.
    float4 an0 = __ldcs(&anchors[a0]);
    float4 an1 = __ldcs(&anchors[a1]);

    float w0  = an0.z - an0.x,      h0  = an0.w - an0.y;
    float cx0 = an0.x + 0.5f * w0,  cy0 = an0.y + 0.5f * h0;
    float iw0 = 1.0f / w0,          ih0 = 1.0f / h0;
    float lw0 = __logf(w0),         lh0 = __logf(h0);

    float w1  = an1.z - an1.x,      h1  = an1.w - an1.y;
    float cx1 = an1.x + 0.5f * w1,  cy1 = an1.y + 0.5f * h1;
    float iw1 = 1.0f / w1,          ih1 = 1.0f / h1;
    float lw1 = __logf(w1),         lh1 = __logf(h1);

    __syncthreads();   // s_w ready

    float s0 = 0.0f, s1 = 0.0f, s2 = 0.0f, s3 = 0.0f;

#pragma unroll
    for (int b = 0; b < B_; b++) {
        // In-loop loads: ptxas hoists/overlaps within its register budget.
        int m0 = (int)__ldcs(&g_m8[(size_t)b * A_ + a0]);
        int m1 = (int)__ldcs(&g_m8[(size_t)b * A_ + a1]);
        const bool f0 = (m0 >= 0);
        const bool f1 = (m1 >= 0);

        float4 r0 = __ldcs(&bbox[(size_t)b * A_ + a0]);
        float4 r1 = __ldcs(&bbox[(size_t)b * A_ + a1]);
        float4 t0 = g_gt[b * G_ + (f0 ? m0 : 0)];  // 32 KB table, L1-resident
        float4 t1 = g_gt[b * G_ + (f1 ? m1 : 0)];

        float dx0 = (t0.x - cx0) * iw0;
        float dy0 = (t0.y - cy0) * ih0;
        float dw0 = t0.z - lw0;
        float dh0 = t0.w - lh0;
        float l10 = fabsf(r0.x - dx0) + fabsf(r0.y - dy0)
                  + fabsf(r0.z - dw0) + fabsf(r0.w - dh0);

        float dx1 = (t1.x - cx1) * iw1;
        float dy1 = (t1.y - cy1) * ih1;
        float dw1 = t1.z - lw1;
        float dh1 = t1.w - lh1;
        float l11 = fabsf(r1.x - dx1) + fabsf(r1.y - dy1)
                  + fabsf(r1.z - dw1) + fabsf(r1.w - dh1);

        float wb = s_w[b];
        float c  = (f0 ? wb * l10 : 0.0f) + (f1 ? wb * l11 : 0.0f);

        if      ((b & 3) == 0) s0 += c;
        else if ((b & 3) == 1) s1 += c;
        else if ((b & 3) == 2) s2 += c;
        else                   s3 += c;
    }

    float s = (s0 + s1) + (s2 + s3);

    // ONE warp reduce per thread for the whole kernel.
#pragma unroll
    for (int o = 16; o > 0; o >>= 1)
        s += __shfl_down_sync(0xffffffffu, s, o);
    if (lane == 0) s_sum[warp] = s;
    __syncthreads();

    if (tid == 0) {
        float bs = 0.0f;
#pragma unroll
        for (int w = 0; w < NWARP; w++) bs += s_sum[w];
        g_bpart[blockIdx.x] = bs;
    }

    // ---- last-block final fold (fixed order -> deterministic) ----
    __threadfence();
    __syncthreads();
    if (tid == 0) s_t = atomicAdd(&g_done2, 1u);
    __syncthreads();

    if (s_t == (unsigned)(NBLK - 1)) {
        float v = 0.0f;
#pragma unroll
        for (int i = 0; i < NBLK / NTHR; i++)     // 8 per thread
            v += __ldcg(&g_bpart[tid + i * NTHR]);
#pragma unroll
        for (int o = 16; o > 0; o >>= 1)
            v += __shfl_down_sync(0xffffffffu, v, o);
        if (lane == 0) s_sum[warp] = v;
        __syncthreads();
        if (tid == 0) {
            float tot = 0.0f;
#pragma unroll
            for (int w = 0; w < NWARP; w++) tot += s_sum[w];
            *out = tot * (1.0f / (float)B_);
            g_done2 = 0;
        }
    }
}

extern "C" void kernel_launch(void* const* d_in, const int* in_sizes, int n_in,
                              void* d_out, int out_size)
{
    const float4* bbox    = (const float4*)d_in[0];  // bbox_regression [B, A, 4] f32
    const float4* anchors = (const float4*)d_in[1];  // anchors [A, 4] f32
    const float4* gt      = (const float4*)d_in[2];  // gt_boxes [B, G, 4] f32
    const int*    midx    = (const int*)d_in[3];     // matched_idxs [B, A] i32

    prep_kernel<<<PBLK, PTHR>>>(gt, midx);
    retina_loss_main<<<NBLK, NTHR>>>(bbox, anchors, (float*)d_out);
}

// round 16
// speedup vs baseline: 1.0230x; 1.0230x over previous
#include <cuda_runtime.h>

#define B_    16
#define A_    262144
#define G_    128

// ---- prep launch: 4096 blocks x 256 thr, thread = 4 anchors of one batch
#define PTHR  256
#define PBLK  (B_ * A_ / (4 * PTHR))   /* 4096 */
#define CHUNKS_PER_B (A_ / (4 * PTHR)) /* 256 */

// ---- main launch: 1024 blocks x 256 thr, thread = 1 anchor (R12 proven)
#define NTHR  256
#define NBLK  (A_ / NTHR)              /* 1024 */
#define NWARP (NTHR / 32)              /* 8 */

// Pre-transformed gt table: {gcx, gcy, log(gw), log(gh)} per (b, g).
__device__ float4      g_gt[B_ * G_];
// int8 shadow of matched_idxs (values fit in [-2, 127]): 4.2 MB vs 16.8 MB.
__device__ signed char g_m8[B_ * A_];
// Per-batch fg counts (int atomics -> deterministic) and weights 1/max(1,n).
__device__ int         g_cnt[B_];
__device__ float       g_w[B_];
// Per-block weighted partials.
__device__ float       g_bpart[NBLK];
__device__ unsigned    g_done1 = 0;
__device__ unsigned    g_done2 = 0;

// ---------------------------------------------------------------------------
// K1 (lean, proven R14): block = (batch, chunk). One int4 load + one char4
// store per thread, one atomicAdd per block. Pre-transforms gt (first 2048).
// ---------------------------------------------------------------------------
__global__ void __launch_bounds__(PTHR)
prep_kernel(const float4* __restrict__ gt, const int* __restrict__ midx)
{
    __shared__ int s_c[PTHR / 32];
    __shared__ unsigned s_t;

    const int tid  = threadIdx.x;
    const int lane = tid & 31;
    const int warp = tid >> 5;

    const int gid = blockIdx.x * PTHR + tid;
    if (gid < B_ * G_) {
        float4 g = gt[gid];
        float gw = g.z - g.x;
        float gh = g.w - g.y;
        g_gt[gid] = make_float4(g.x + 0.5f * gw, g.y + 0.5f * gh,
                                __logf(gw), __logf(gh));
    }

    const int b     = blockIdx.x >> 8;          // / CHUNKS_PER_B
    const int chunk = blockIdx.x & (CHUNKS_PER_B - 1);
    const int idx   = b * A_ + chunk * (4 * PTHR) + tid * 4;

    int4 mv = __ldcs(reinterpret_cast<const int4*>(&midx[idx]));  // 16B load
    char4 pk;
    pk.x = (char)mv.x; pk.y = (char)mv.y; pk.z = (char)mv.z; pk.w = (char)mv.w;
    *reinterpret_cast<char4*>(&g_m8[idx]) = pk;                   // 4B store

    int c = (mv.x >= 0) + (mv.y >= 0) + (mv.z >= 0) + (mv.w >= 0);
#pragma unroll
    for (int o = 16; o > 0; o >>= 1)
        c += __shfl_down_sync(0xffffffffu, c, o);
    if (lane == 0) s_c[warp] = c;
    __syncthreads();

    if (tid == 0) {
        int tot = 0;
#pragma unroll
        for (int w = 0; w < PTHR / 32; w++) tot += s_c[w];
        atomicAdd(&g_cnt[b], tot);          // 4096 atomics total, 256/addr
        __threadfence();
        s_t = atomicAdd(&g_done1, 1u);
    }
    __syncthreads();

    if (s_t == (unsigned)(PBLK - 1)) {
        if (tid < B_) {
            int cc = g_cnt[tid];
            g_w[tid]   = 1.0f / (float)(cc > 1 ? cc : 1);
            g_cnt[tid] = 0;                 // reset for next graph replay
        }
        if (tid == 0) g_done1 = 0;
    }
}

// ---------------------------------------------------------------------------
// K2 (exact R12 main — best measured: 21.6us ncu, occ 94.6%): single anchor
// per thread, int8 midx front-batched, smem weight broadcast, 4 rotating
// accumulators, one warp reduce, fused last-block fold.
// ---------------------------------------------------------------------------
__global__ void __launch_bounds__(NTHR, 7)
retina_loss_main(const float4* __restrict__ bbox,     // [B, A, 4]
                 const float4* __restrict__ anchors,  // [A, 4]
                 float*        __restrict__ out)
{
    __shared__ float s_w[B_];
    __shared__ float s_sum[NWARP];
    __shared__ unsigned s_t;

    const int tid  = threadIdx.x;
    const int lane = tid & 31;
    const int warp = tid >> 5;
    const int a    = blockIdx.x * NTHR + tid;   // NBLK*NTHR == A_

    if (tid < B_) s_w[tid] = g_w[tid];

    // Anchor loaded ONCE, reused for all 16 batches.
    float4 an = __ldcs(&anchors[a]);
    float ex_w  = an.z - an.x;
    float ex_h  = an.w - an.y;
    float ex_cx = an.x + 0.5f * ex_w;
    float ex_cy = an.y + 0.5f * ex_h;
    float iw   = 1.0f / ex_w;
    float ih   = 1.0f / ex_h;
    float lexw = __logf(ex_w);
    float lexh = __logf(ex_h);

    // Front-batch all 16 matched-index byte loads (coalesced, 1 sector/warp).
    int m[B_];
#pragma unroll
    for (int b = 0; b < B_; b++)
        m[b] = (int)__ldcs(&g_m8[(size_t)b * A_ + a]);

    __syncthreads();   // s_w ready

    float s0 = 0.0f, s1 = 0.0f, s2 = 0.0f, s3 = 0.0f;

#pragma unroll
    for (int b = 0; b < B_; b++) {
        const bool fg = (m[b] >= 0);
        float4 r = __ldcs(&bbox[(size_t)b * A_ + a]);
        float4 t = g_gt[b * G_ + (fg ? m[b] : 0)];  // 32 KB table, L1-resident

        float dx = (t.x - ex_cx) * iw;
        float dy = (t.y - ex_cy) * ih;
        float dw = t.z - lexw;     // log(gw) - log(ex_w)
        float dh = t.w - lexh;

        float l1 = fabsf(r.x - dx) + fabsf(r.y - dy)
                 + fabsf(r.z - dw) + fabsf(r.w - dh);
        float c  = fg ? s_w[b] * l1 : 0.0f;

        // 4 rotating accumulators: dependency chain length B_/4.
        if      ((b & 3) == 0) s0 += c;
        else if ((b & 3) == 1) s1 += c;
        else if ((b & 3) == 2) s2 += c;
        else                   s3 += c;
    }

    float s = (s0 + s1) + (s2 + s3);

    // ONE warp reduce for the whole thread.
#pragma unroll
    for (int o = 16; o > 0; o >>= 1)
        s += __shfl_down_sync(0xffffffffu, s, o);
    if (lane == 0) s_sum[warp] = s;
    __syncthreads();

    if (tid == 0) {
        float bs = 0.0f;
#pragma unroll
        for (int w = 0; w < NWARP; w++) bs += s_sum[w];
        g_bpart[blockIdx.x] = bs;
    }

    // ---- last-block final fold (fixed order -> deterministic) ----
    __threadfence();
    __syncthreads();
    if (tid == 0) s_t = atomicAdd(&g_done2, 1u);
    __syncthreads();

    if (s_t == (unsigned)(NBLK - 1)) {
        float v = 0.0f;
#pragma unroll
        for (int i = 0; i < NBLK / NTHR; i++)     // 4 per thread
            v += __ldcg(&g_bpart[tid + i * NTHR]);
#pragma unroll
        for (int o = 16; o > 0; o >>= 1)
            v += __shfl_down_sync(0xffffffffu, v, o);
        if (lane == 0) s_sum[warp] = v;
        __syncthreads();
        if (tid == 0) {
            float tot = 0.0f;
#pragma unroll
            for (int w = 0; w < NWARP; w++) tot += s_sum[w];
            *out = tot * (1.0f / (float)B_);
            g_done2 = 0;
        }
    }
}

extern "C" void kernel_launch(void* const* d_in, const int* in_sizes, int n_in,
                              void* d_out, int out_size)
{
    const float4* bbox    = (const float4*)d_in[0];  // bbox_regression [B, A, 4] f32
    const float4* anchors = (const float4*)d_in[1];  // anchors [A, 4] f32
    const float4* gt      = (const float4*)d_in[2];  // gt_boxes [B, G, 4] f32
    const int*    midx    = (const int*)d_in[3];     // matched_idxs [B, A] i32

    prep_kernel<<<PBLK, PTHR>>>(gt, midx);
    retina_loss_main<<<NBLK, NTHR>>>(bbox, anchors, (float*)d_out);
}